// round 6
// baseline (speedup 1.0000x reference)
#include <cuda_runtime.h>
#include <cuda_fp16.h>
#include <math.h>
#include <stdint.h>

#define NN   50000
#define EE   800000
#define D    128
#define DOUT 10
#define GG   128
#define NB   250
#define CH   200

// ---------------- device scratch ----------------
__device__ __half g_h0[(size_t)NN * D];
__device__ __half g_h1[(size_t)NN * D];
__device__ int    g_deg[NN];
__device__ float  g_dinv[NN];
__device__ int    g_rowptr[NN + 1];
__device__ int    g_fill[NN];
__device__ int    g_colsrc[EE];
__device__ int    g_blocksum[NB];
__device__ float  g_psum[GG * D];
__device__ int    g_pcnt[GG];

// ---------------- CSR build ----------------
__global__ void k_init() {
    int i = blockIdx.x * blockDim.x + threadIdx.x;
    if (i < NN) { g_deg[i] = 1; g_fill[i] = 0; }
    if (i < GG * D) g_psum[i] = 0.0f;
    if (i < GG) g_pcnt[i] = 0;
}

__global__ void k_count(const int* __restrict__ ei) {
    int e = blockIdx.x * blockDim.x + threadIdx.x;
    if (e < EE) atomicAdd(&g_deg[ei[EE + e]], 1);
}

__global__ void k_partial() {
    __shared__ int red[256];
    const int b = blockIdx.x, t = threadIdx.x;
    int v = 0;
    if (t < CH) {
        int i = b * CH + t;
        int dg = g_deg[i];
        g_dinv[i] = rsqrtf((float)dg);
        v = dg - 1;
    }
    red[t] = v;
    __syncthreads();
    for (int off = 128; off > 0; off >>= 1) {
        if (t < off) red[t] += red[t + off];
        __syncthreads();
    }
    if (t == 0) g_blocksum[b] = red[0];
}

// fused: per-block base reduction + per-chunk exclusive scan -> rowptr
__global__ void k_rowptr() {
    __shared__ int s[256];
    __shared__ int base_sh;
    const int b = blockIdx.x, t = threadIdx.x;

    // phase 1: base = sum(blocksum[0..b))
    s[t] = (t < b) ? g_blocksum[t] : 0;
    __syncthreads();
    for (int off = 128; off > 0; off >>= 1) {
        if (t < off) s[t] += s[t + off];
        __syncthreads();
    }
    if (t == 0) base_sh = s[0];
    __syncthreads();
    const int base = base_sh;
    __syncthreads();

    // phase 2: inclusive scan of (deg-1) within chunk
    int v = 0;
    if (t < CH) v = g_deg[b * CH + t] - 1;
    s[t] = v;
    __syncthreads();
    for (int off = 1; off < 256; off <<= 1) {
        int u = (t >= off) ? s[t - off] : 0;
        __syncthreads();
        s[t] += u;
        __syncthreads();
    }
    if (t < CH) g_rowptr[b * CH + t] = base + s[t] - v;
    if (b == NB - 1 && t == CH - 1) g_rowptr[NN] = base + s[t];
}

__global__ void k_fill(const int* __restrict__ ei) {
    int e = blockIdx.x * blockDim.x + threadIdx.x;
    if (e < EE) {
        int d = ei[EE + e];
        int s = ei[e];
        int pos = atomicAdd(&g_fill[d], 1);
        g_colsrc[g_rowptr[d] + pos] = s;
    }
}

// ---------------- fp16 tensor-core GEMM, M=64 tiles ----------------
// Block 256 thr (8 warps), tile 64x128x128, warps 2(M)x4(N), 4 CTAs/SM.
#define SMSH 136
#define GEMM_SMEM ((64 + 128) * SMSH * sizeof(__half))   // 52.2 KB

#define MMA_F16(cc, a0, a1, a2, a3, b0, b1)                               \
    asm volatile("mma.sync.aligned.m16n8k16.row.col.f32.f16.f16.f32 "     \
                 "{%0,%1,%2,%3}, {%4,%5,%6,%7}, {%8,%9}, {%0,%1,%2,%3};"  \
                 : "+f"(cc[0]), "+f"(cc[1]), "+f"(cc[2]), "+f"(cc[3])     \
                 : "r"(a0), "r"(a1), "r"(a2), "r"(a3), "r"(b0), "r"(b1))

template <bool IN_HALF, bool RELU>
__global__ void __launch_bounds__(256, 4)
k_gemm_h(const void* __restrict__ Ain, const float* __restrict__ W,
         __half* __restrict__ C) {
    extern __shared__ __half smh[];
    __half* As = smh;                // [64][136]
    __half* Wt = smh + 64 * SMSH;    // [128][136]  Wt[n][k]
    const int t = threadIdx.x;
    const int row0 = blockIdx.x * 64;

    // stage Wt (transpose W[k][n] -> Wt[n][k], fp32 -> fp16)
    for (int idx = t; idx < D * D; idx += 256) {
        int k = idx >> 7, n = idx & 127;
        Wt[n * SMSH + k] = __float2half_rn(W[idx]);
    }

    // stage As
    if (IN_HALF) {
        const __half* A = (const __half*)Ain;
        const __half2 z2 = __float2half2_rn(0.f);
        for (int j = t; j < (64 * D) / 8; j += 256) {
            int r = j >> 4;
            int c8 = (j & 15) * 8;
            uint4 u = make_uint4(0, 0, 0, 0);
            if (row0 + r < NN)
                u = *(const uint4*)(A + (size_t)(row0 + r) * D + c8);
            if (RELU) {
                __half2* h = (__half2*)&u;
                #pragma unroll
                for (int q = 0; q < 4; q++) h[q] = __hmax2(h[q], z2);
            }
            *(uint4*)(As + r * SMSH + c8) = u;
        }
    } else {
        const float* A = (const float*)Ain;
        for (int j = t; j < (64 * D) / 4; j += 256) {
            int r = j >> 5;
            int c4 = (j & 31) * 4;
            float4 v = make_float4(0.f, 0.f, 0.f, 0.f);
            if (row0 + r < NN)
                v = *(const float4*)(A + (size_t)(row0 + r) * D + c4);
            __half2 h01 = __floats2half2_rn(v.x, v.y);
            __half2 h23 = __floats2half2_rn(v.z, v.w);
            uint2 u;
            u.x = *(uint32_t*)&h01;
            u.y = *(uint32_t*)&h23;
            *(uint2*)(As + r * SMSH + c4) = u;
        }
    }
    __syncthreads();

    const int w    = t >> 5;
    const int lane = t & 31;
    const int wm   = w & 1;     // 2 warps in M: rows [wm*32, +32)
    const int wn   = w >> 1;    // 4 warps in N: cols [wn*32, +32)
    const int quad = lane >> 2;
    const int rem  = lane & 3;

    float acc[2][4][4];
    #pragma unroll
    for (int m = 0; m < 2; m++)
        #pragma unroll
        for (int j = 0; j < 4; j++)
            #pragma unroll
            for (int r = 0; r < 4; r++) acc[m][j][r] = 0.f;

    const __half* Ab = As + (wm * 32 + quad) * SMSH + 2 * rem;
    const __half* Bb = Wt + (wn * 32 + quad) * SMSH + 2 * rem;

    #pragma unroll
    for (int ks = 0; ks < 8; ks++) {
        const int k0 = ks * 16;
        uint32_t a[2][4];
        #pragma unroll
        for (int m = 0; m < 2; m++) {
            const __half* p = Ab + m * 16 * SMSH + k0;
            a[m][0] = *(const uint32_t*)(p);
            a[m][1] = *(const uint32_t*)(p + 8 * SMSH);
            a[m][2] = *(const uint32_t*)(p + 8);
            a[m][3] = *(const uint32_t*)(p + 8 * SMSH + 8);
        }
        #pragma unroll
        for (int j = 0; j < 4; j++) {
            const __half* q = Bb + j * 8 * SMSH + k0;
            uint32_t b0 = *(const uint32_t*)(q);
            uint32_t b1 = *(const uint32_t*)(q + 8);
            MMA_F16(acc[0][j], a[0][0], a[0][1], a[0][2], a[0][3], b0, b1);
            MMA_F16(acc[1][j], a[1][0], a[1][1], a[1][2], a[1][3], b0, b1);
        }
    }

    #pragma unroll
    for (int m = 0; m < 2; m++) {
        int r = row0 + wm * 32 + m * 16 + quad;
        #pragma unroll
        for (int j = 0; j < 4; j++) {
            int cb = wn * 32 + j * 8 + rem * 2;
            if (r < NN) {
                __half2 h = __floats2half2_rn(acc[m][j][0], acc[m][j][1]);
                *(uint32_t*)(C + (size_t)r * D + cb) = *(uint32_t*)&h;
            }
            if (r + 8 < NN) {
                __half2 h = __floats2half2_rn(acc[m][j][2], acc[m][j][3]);
                *(uint32_t*)(C + (size_t)(r + 8) * D + cb) = *(uint32_t*)&h;
            }
        }
    }
}

// ---------------- aggregation: TWO nodes per warp (2x MLP) ----------------
__device__ __forceinline__ void agg_accum(const __half* H, int s, float ds,
                                          int lane, float* acc) {
    uint2 u = ((const uint2*)(H + (size_t)s * D))[lane];
    __half2 p0 = *(__half2*)&u.x;
    __half2 p1 = *(__half2*)&u.y;
    float2 f0 = __half22float2(p0);
    float2 f1 = __half22float2(p1);
    acc[0] += f0.x * ds; acc[1] += f0.y * ds;
    acc[2] += f1.x * ds; acc[3] += f1.y * ds;
}

__device__ __forceinline__ void agg_core(const __half* __restrict__ H, int i0, int i1,
                                         int lane, float* a0, float* a1,
                                         float di0, float di1) {
    agg_accum(H, i0, di0, lane, a0);
    agg_accum(H, i1, di1, lane, a1);

    int e0 = g_rowptr[i0];
    const int e0e = g_rowptr[i0 + 1];
    int e1 = g_rowptr[i1];
    const int e1e = g_rowptr[i1 + 1];

    while (e0 < e0e && e1 < e1e) {
        int s0 = g_colsrc[e0++];
        int s1 = g_colsrc[e1++];
        float d0 = g_dinv[s0];
        float d1 = g_dinv[s1];
        agg_accum(H, s0, d0, lane, a0);
        agg_accum(H, s1, d1, lane, a1);
    }
    while (e0 < e0e) {
        int s0 = g_colsrc[e0++];
        agg_accum(H, s0, g_dinv[s0], lane, a0);
    }
    while (e1 < e1e) {
        int s1 = g_colsrc[e1++];
        agg_accum(H, s1, g_dinv[s1], lane, a1);
    }
}

__global__ void k_agg(const __half* __restrict__ H, const float* __restrict__ bias,
                      __half* __restrict__ O) {
    int pair = (blockIdx.x * blockDim.x + threadIdx.x) >> 5;
    int lane = threadIdx.x & 31;
    const int i0 = pair * 2, i1 = pair * 2 + 1;
    if (i0 >= NN) return;               // NN even -> i1 valid whenever i0 is

    const float di0 = g_dinv[i0], di1 = g_dinv[i1];
    float a0[4] = {0.f, 0.f, 0.f, 0.f};
    float a1[4] = {0.f, 0.f, 0.f, 0.f};
    agg_core(H, i0, i1, lane, a0, a1, di0, di1);

    float4 b4 = ((const float4*)bias)[lane];
    {
        __half2 o01 = __floats2half2_rn(a0[0] * di0 + b4.x, a0[1] * di0 + b4.y);
        __half2 o23 = __floats2half2_rn(a0[2] * di0 + b4.z, a0[3] * di0 + b4.w);
        uint2 u; u.x = *(uint32_t*)&o01; u.y = *(uint32_t*)&o23;
        ((uint2*)(O + (size_t)i0 * D))[lane] = u;
    }
    {
        __half2 o01 = __floats2half2_rn(a1[0] * di1 + b4.x, a1[1] * di1 + b4.y);
        __half2 o23 = __floats2half2_rn(a1[2] * di1 + b4.z, a1[3] * di1 + b4.w);
        uint2 u; u.x = *(uint32_t*)&o01; u.y = *(uint32_t*)&o23;
        ((uint2*)(O + (size_t)i1 * D))[lane] = u;
    }
}

__global__ void k_agg_pool(const __half* __restrict__ H, const float* __restrict__ bias,
                           const int* __restrict__ batch) {
    int pair = (blockIdx.x * blockDim.x + threadIdx.x) >> 5;
    int lane = threadIdx.x & 31;
    const int i0 = pair * 2, i1 = pair * 2 + 1;
    if (i0 >= NN) return;

    const float di0 = g_dinv[i0], di1 = g_dinv[i1];
    float a0[4] = {0.f, 0.f, 0.f, 0.f};
    float a1[4] = {0.f, 0.f, 0.f, 0.f};
    agg_core(H, i0, i1, lane, a0, a1, di0, di1);

    float4 b4 = ((const float4*)bias)[lane];
    const int g0 = batch[i0], g1 = batch[i1];
    float* d0 = g_psum + g0 * D + lane * 4;
    atomicAdd(d0 + 0, a0[0] * di0 + b4.x);
    atomicAdd(d0 + 1, a0[1] * di0 + b4.y);
    atomicAdd(d0 + 2, a0[2] * di0 + b4.z);
    atomicAdd(d0 + 3, a0[3] * di0 + b4.w);
    float* d1 = g_psum + g1 * D + lane * 4;
    atomicAdd(d1 + 0, a1[0] * di1 + b4.x);
    atomicAdd(d1 + 1, a1[1] * di1 + b4.y);
    atomicAdd(d1 + 2, a1[2] * di1 + b4.z);
    atomicAdd(d1 + 3, a1[3] * di1 + b4.w);
    if (lane == 0) { atomicAdd(&g_pcnt[g0], 1); atomicAdd(&g_pcnt[g1], 1); }
}

// ---------------- head ----------------
__global__ void k_final(const float* __restrict__ Wl, const float* __restrict__ bl,
                        float* __restrict__ out) {
    int g = threadIdx.x;
    if (g >= GG) return;
    float cnt = (float)g_pcnt[g];
    float inv = 1.0f / fmaxf(cnt, 1.0f);
    float logits[DOUT];
    #pragma unroll
    for (int d = 0; d < DOUT; d++) logits[d] = bl[d];
    for (int f = 0; f < D; f++) {
        float p = g_psum[g * D + f] * inv;
        #pragma unroll
        for (int d = 0; d < DOUT; d++)
            logits[d] += p * Wl[f * DOUT + d];
    }
    float m = logits[0];
    #pragma unroll
    for (int d = 1; d < DOUT; d++) m = fmaxf(m, logits[d]);
    float sum = 0.f;
    #pragma unroll
    for (int d = 0; d < DOUT; d++) sum += expf(logits[d] - m);
    float lse = m + logf(sum);
    #pragma unroll
    for (int d = 0; d < DOUT; d++) out[g * DOUT + d] = logits[d] - lse;
}

// ---------------- launch ----------------
extern "C" void kernel_launch(void* const* d_in, const int* in_sizes, int n_in,
                              void* d_out, int out_size) {
    const float* x     = (const float*)d_in[0];
    const int*   ei    = (const int*)d_in[1];
    const int*   batch = (const int*)d_in[2];
    const float* W1 = (const float*)d_in[3];
    const float* b1 = (const float*)d_in[4];
    const float* W2 = (const float*)d_in[5];
    const float* b2 = (const float*)d_in[6];
    const float* W3 = (const float*)d_in[7];
    const float* b3 = (const float*)d_in[8];
    const float* Wl = (const float*)d_in[9];
    const float* bl = (const float*)d_in[10];
    float* out = (float*)d_out;

    cudaFuncSetAttribute(k_gemm_h<false, false>,
                         cudaFuncAttributeMaxDynamicSharedMemorySize, (int)GEMM_SMEM);
    cudaFuncSetAttribute(k_gemm_h<true, true>,
                         cudaFuncAttributeMaxDynamicSharedMemorySize, (int)GEMM_SMEM);

    __half *h0, *h1;
    cudaGetSymbolAddress((void**)&h0, g_h0);
    cudaGetSymbolAddress((void**)&h1, g_h1);

    const int TB = 256;
    // CSR build (5 kernels)
    k_init   <<<(NN + TB - 1) / TB, TB>>>();
    k_count  <<<(EE + TB - 1) / TB, TB>>>(ei);
    k_partial<<<NB, 256>>>();
    k_rowptr <<<NB, 256>>>();
    k_fill   <<<(EE + TB - 1) / TB, TB>>>(ei);

    const int gemm_grid = (NN + 63) / 64;                 // 782
    const int agg_grid  = ((NN / 2) * 32 + TB - 1) / TB;  // 3125

    // layer 1
    k_gemm_h<false, false><<<gemm_grid, TB, GEMM_SMEM>>>(x,  W1, h0);
    k_agg<<<agg_grid, TB>>>(h0, b1, h1);
    // layer 2
    k_gemm_h<true, true><<<gemm_grid, TB, GEMM_SMEM>>>(h1, W2, h0);
    k_agg<<<agg_grid, TB>>>(h0, b2, h1);
    // layer 3 (agg fused with pool)
    k_gemm_h<true, true><<<gemm_grid, TB, GEMM_SMEM>>>(h1, W3, h0);
    k_agg_pool<<<agg_grid, TB>>>(h0, b3, batch);

    // head
    k_final<<<1, 128>>>(Wl, bl, out);
}

// round 7
// speedup vs baseline: 1.0333x; 1.0333x over previous
#include <cuda_runtime.h>
#include <cuda_fp16.h>
#include <math.h>
#include <stdint.h>

#define NN   50000
#define EE   800000
#define D    128
#define DOUT 10
#define GG   128
#define NB   250
#define CH   200

// ---------------- device scratch ----------------
__device__ __half g_h0[(size_t)NN * D];
__device__ __half g_h1[(size_t)NN * D];
__device__ int    g_deg[NN];
__device__ float  g_dinv[NN];
__device__ int    g_rowptr[NN + 1];
__device__ int    g_fill[NN];
__device__ int    g_colsrc[EE];
__device__ int    g_blocksum[NB];
__device__ float  g_psum[GG * D];
__device__ int    g_pcnt[GG];

// ---------------- CSR build ----------------
__global__ void k_init() {
    int i = blockIdx.x * blockDim.x + threadIdx.x;
    if (i < NN) { g_deg[i] = 1; g_fill[i] = 0; }
    if (i < GG * D) g_psum[i] = 0.0f;
    if (i < GG) g_pcnt[i] = 0;
}

__global__ void k_count(const int* __restrict__ ei) {
    int e = blockIdx.x * blockDim.x + threadIdx.x;
    if (e < EE) atomicAdd(&g_deg[ei[EE + e]], 1);
}

__global__ void k_partial() {
    __shared__ int red[256];
    const int b = blockIdx.x, t = threadIdx.x;
    int v = 0;
    if (t < CH) {
        int i = b * CH + t;
        int dg = g_deg[i];
        g_dinv[i] = rsqrtf((float)dg);
        v = dg - 1;
    }
    red[t] = v;
    __syncthreads();
    for (int off = 128; off > 0; off >>= 1) {
        if (t < off) red[t] += red[t + off];
        __syncthreads();
    }
    if (t == 0) g_blocksum[b] = red[0];
}

// fused: per-block base reduction + per-chunk exclusive scan -> rowptr
__global__ void k_rowptr() {
    __shared__ int s[256];
    __shared__ int base_sh;
    const int b = blockIdx.x, t = threadIdx.x;

    s[t] = (t < b) ? g_blocksum[t] : 0;
    __syncthreads();
    for (int off = 128; off > 0; off >>= 1) {
        if (t < off) s[t] += s[t + off];
        __syncthreads();
    }
    if (t == 0) base_sh = s[0];
    __syncthreads();
    const int base = base_sh;
    __syncthreads();

    int v = 0;
    if (t < CH) v = g_deg[b * CH + t] - 1;
    s[t] = v;
    __syncthreads();
    for (int off = 1; off < 256; off <<= 1) {
        int u = (t >= off) ? s[t - off] : 0;
        __syncthreads();
        s[t] += u;
        __syncthreads();
    }
    if (t < CH) g_rowptr[b * CH + t] = base + s[t] - v;
    if (b == NB - 1 && t == CH - 1) g_rowptr[NN] = base + s[t];
}

__global__ void k_fill(const int* __restrict__ ei) {
    int e = blockIdx.x * blockDim.x + threadIdx.x;
    if (e < EE) {
        int d = ei[EE + e];
        int s = ei[e];
        int pos = atomicAdd(&g_fill[d], 1);
        g_colsrc[g_rowptr[d] + pos] = s;
    }
}

// ---------------- fp16 tensor-core GEMM (M=128 tiles, 2 CTA/SM) ----------------
#define SMSH 136
#define GEMM_SMEM (2 * 128 * SMSH * sizeof(__half))

#define MMA_F16(cc, a0, a1, a2, a3, b0, b1)                               \
    asm volatile("mma.sync.aligned.m16n8k16.row.col.f32.f16.f16.f32 "     \
                 "{%0,%1,%2,%3}, {%4,%5,%6,%7}, {%8,%9}, {%0,%1,%2,%3};"  \
                 : "+f"(cc[0]), "+f"(cc[1]), "+f"(cc[2]), "+f"(cc[3])     \
                 : "r"(a0), "r"(a1), "r"(a2), "r"(a3), "r"(b0), "r"(b1))

template <bool IN_HALF, bool RELU>
__global__ void __launch_bounds__(256, 2)
k_gemm_h(const void* __restrict__ Ain, const float* __restrict__ W,
         __half* __restrict__ C) {
    extern __shared__ __half smh[];
    __half* As = smh;                 // [128][136]
    __half* Wt = smh + 128 * SMSH;    // [128][136]  Wt[n][k]
    const int t = threadIdx.x;
    const int row0 = blockIdx.x * 128;

    for (int idx = t; idx < D * D; idx += 256) {
        int k = idx >> 7, n = idx & 127;
        Wt[n * SMSH + k] = __float2half_rn(W[idx]);
    }

    if (IN_HALF) {
        const __half* A = (const __half*)Ain;
        const __half2 z2 = __float2half2_rn(0.f);
        for (int j = t; j < (128 * D) / 8; j += 256) {
            int r = j >> 4;
            int c8 = (j & 15) * 8;
            uint4 u = make_uint4(0, 0, 0, 0);
            if (row0 + r < NN)
                u = *(const uint4*)(A + (size_t)(row0 + r) * D + c8);
            if (RELU) {
                __half2* h = (__half2*)&u;
                #pragma unroll
                for (int q = 0; q < 4; q++) h[q] = __hmax2(h[q], z2);
            }
            *(uint4*)(As + r * SMSH + c8) = u;
        }
    } else {
        const float* A = (const float*)Ain;
        for (int j = t; j < (128 * D) / 4; j += 256) {
            int r = j >> 5;
            int c4 = (j & 31) * 4;
            float4 v = make_float4(0.f, 0.f, 0.f, 0.f);
            if (row0 + r < NN)
                v = *(const float4*)(A + (size_t)(row0 + r) * D + c4);
            __half2 h01 = __floats2half2_rn(v.x, v.y);
            __half2 h23 = __floats2half2_rn(v.z, v.w);
            uint2 u;
            u.x = *(uint32_t*)&h01;
            u.y = *(uint32_t*)&h23;
            *(uint2*)(As + r * SMSH + c4) = u;
        }
    }
    __syncthreads();

    const int w    = t >> 5;
    const int lane = t & 31;
    const int wm   = w & 3;
    const int wn   = w >> 2;
    const int quad = lane >> 2;
    const int rem  = lane & 3;

    float acc[2][8][4];
    #pragma unroll
    for (int m = 0; m < 2; m++)
        #pragma unroll
        for (int j = 0; j < 8; j++)
            #pragma unroll
            for (int r = 0; r < 4; r++) acc[m][j][r] = 0.f;

    const __half* Ab = As + (wm * 32 + quad) * SMSH + 2 * rem;
    const __half* Bb = Wt + (wn * 64 + quad) * SMSH + 2 * rem;

    #pragma unroll
    for (int ks = 0; ks < 8; ks++) {
        const int k0 = ks * 16;
        uint32_t a[2][4];
        #pragma unroll
        for (int m = 0; m < 2; m++) {
            const __half* p = Ab + m * 16 * SMSH + k0;
            a[m][0] = *(const uint32_t*)(p);
            a[m][1] = *(const uint32_t*)(p + 8 * SMSH);
            a[m][2] = *(const uint32_t*)(p + 8);
            a[m][3] = *(const uint32_t*)(p + 8 * SMSH + 8);
        }
        #pragma unroll
        for (int j = 0; j < 8; j++) {
            const __half* q = Bb + j * 8 * SMSH + k0;
            uint32_t b0 = *(const uint32_t*)(q);
            uint32_t b1 = *(const uint32_t*)(q + 8);
            MMA_F16(acc[0][j], a[0][0], a[0][1], a[0][2], a[0][3], b0, b1);
            MMA_F16(acc[1][j], a[1][0], a[1][1], a[1][2], a[1][3], b0, b1);
        }
    }

    #pragma unroll
    for (int m = 0; m < 2; m++) {
        int r = row0 + wm * 32 + m * 16 + quad;
        #pragma unroll
        for (int j = 0; j < 8; j++) {
            int cb = wn * 64 + j * 8 + rem * 2;
            if (r < NN) {
                __half2 h = __floats2half2_rn(acc[m][j][0], acc[m][j][1]);
                *(uint32_t*)(C + (size_t)r * D + cb) = *(uint32_t*)&h;
            }
            if (r + 8 < NN) {
                __half2 h = __floats2half2_rn(acc[m][j][2], acc[m][j][3]);
                *(uint32_t*)(C + (size_t)(r + 8) * D + cb) = *(uint32_t*)&h;
            }
        }
    }
}

// ---------------- aggregation: one node per warp, edge loop unrolled x4 ----------------
__device__ __forceinline__ void agg_accum(const __half* H, int s, float ds,
                                          int lane, float* acc) {
    uint2 u = ((const uint2*)(H + (size_t)s * D))[lane];
    __half2 p0 = *(__half2*)&u.x;
    __half2 p1 = *(__half2*)&u.y;
    float2 f0 = __half22float2(p0);
    float2 f1 = __half22float2(p1);
    acc[0] += f0.x * ds; acc[1] += f0.y * ds;
    acc[2] += f1.x * ds; acc[3] += f1.y * ds;
}

__device__ __forceinline__ void agg_edges(const __half* __restrict__ H, int i,
                                          int lane, float di, float* acc) {
    agg_accum(H, i, di, lane, acc);         // self loop
    int e = g_rowptr[i];
    const int ee = g_rowptr[i + 1];
    for (; e + 4 <= ee; e += 4) {
        int s0 = g_colsrc[e + 0];
        int s1 = g_colsrc[e + 1];
        int s2 = g_colsrc[e + 2];
        int s3 = g_colsrc[e + 3];
        float d0 = g_dinv[s0], d1 = g_dinv[s1];
        float d2 = g_dinv[s2], d3 = g_dinv[s3];
        agg_accum(H, s0, d0, lane, acc);
        agg_accum(H, s1, d1, lane, acc);
        agg_accum(H, s2, d2, lane, acc);
        agg_accum(H, s3, d3, lane, acc);
    }
    for (; e < ee; e++) {
        int s = g_colsrc[e];
        agg_accum(H, s, g_dinv[s], lane, acc);
    }
}

__global__ void k_agg(const __half* __restrict__ H, const float* __restrict__ bias,
                      __half* __restrict__ O) {
    int i = (blockIdx.x * blockDim.x + threadIdx.x) >> 5;
    int lane = threadIdx.x & 31;
    if (i >= NN) return;
    const float di = g_dinv[i];

    float acc[4] = {0.f, 0.f, 0.f, 0.f};
    agg_edges(H, i, lane, di, acc);

    float4 b4 = ((const float4*)bias)[lane];
    __half2 o01 = __floats2half2_rn(acc[0] * di + b4.x, acc[1] * di + b4.y);
    __half2 o23 = __floats2half2_rn(acc[2] * di + b4.z, acc[3] * di + b4.w);
    uint2 u;
    u.x = *(uint32_t*)&o01;
    u.y = *(uint32_t*)&o23;
    ((uint2*)(O + (size_t)i * D))[lane] = u;
}

__global__ void k_agg_pool(const __half* __restrict__ H, const float* __restrict__ bias,
                           const int* __restrict__ batch) {
    int i = (blockIdx.x * blockDim.x + threadIdx.x) >> 5;
    int lane = threadIdx.x & 31;
    if (i >= NN) return;
    const float di = g_dinv[i];

    float acc[4] = {0.f, 0.f, 0.f, 0.f};
    agg_edges(H, i, lane, di, acc);

    float4 b4 = ((const float4*)bias)[lane];
    const int g = batch[i];
    float* dst = g_psum + g * D + lane * 4;
    atomicAdd(dst + 0, acc[0] * di + b4.x);
    atomicAdd(dst + 1, acc[1] * di + b4.y);
    atomicAdd(dst + 2, acc[2] * di + b4.z);
    atomicAdd(dst + 3, acc[3] * di + b4.w);
    if (lane == 0) atomicAdd(&g_pcnt[g], 1);
}

// ---------------- head ----------------
__global__ void k_final(const float* __restrict__ Wl, const float* __restrict__ bl,
                        float* __restrict__ out) {
    int g = threadIdx.x;
    if (g >= GG) return;
    float cnt = (float)g_pcnt[g];
    float inv = 1.0f / fmaxf(cnt, 1.0f);
    float logits[DOUT];
    #pragma unroll
    for (int d = 0; d < DOUT; d++) logits[d] = bl[d];
    for (int f = 0; f < D; f++) {
        float p = g_psum[g * D + f] * inv;
        #pragma unroll
        for (int d = 0; d < DOUT; d++)
            logits[d] += p * Wl[f * DOUT + d];
    }
    float m = logits[0];
    #pragma unroll
    for (int d = 1; d < DOUT; d++) m = fmaxf(m, logits[d]);
    float sum = 0.f;
    #pragma unroll
    for (int d = 0; d < DOUT; d++) sum += expf(logits[d] - m);
    float lse = m + logf(sum);
    #pragma unroll
    for (int d = 0; d < DOUT; d++) out[g * DOUT + d] = logits[d] - lse;
}

// ---------------- launch ----------------
extern "C" void kernel_launch(void* const* d_in, const int* in_sizes, int n_in,
                              void* d_out, int out_size) {
    const float* x     = (const float*)d_in[0];
    const int*   ei    = (const int*)d_in[1];
    const int*   batch = (const int*)d_in[2];
    const float* W1 = (const float*)d_in[3];
    const float* b1 = (const float*)d_in[4];
    const float* W2 = (const float*)d_in[5];
    const float* b2 = (const float*)d_in[6];
    const float* W3 = (const float*)d_in[7];
    const float* b3 = (const float*)d_in[8];
    const float* Wl = (const float*)d_in[9];
    const float* bl = (const float*)d_in[10];
    float* out = (float*)d_out;

    cudaFuncSetAttribute(k_gemm_h<false, false>,
                         cudaFuncAttributeMaxDynamicSharedMemorySize, (int)GEMM_SMEM);
    cudaFuncSetAttribute(k_gemm_h<true, true>,
                         cudaFuncAttributeMaxDynamicSharedMemorySize, (int)GEMM_SMEM);

    __half *h0, *h1;
    cudaGetSymbolAddress((void**)&h0, g_h0);
    cudaGetSymbolAddress((void**)&h1, g_h1);

    const int TB = 256;
    const int gemm_grid = (NN + 127) / 128;           // 391
    const int agg_grid  = (NN * 32 + TB - 1) / TB;    // 6250

    // Fork a side stream: CSR build runs concurrently with GEMM1
    // (GEMM1 depends only on x, W1; aggregation needs both).
    cudaStream_t s2;
    cudaStreamCreate(&s2);
    cudaEvent_t evFork, evJoin;
    cudaEventCreateWithFlags(&evFork, cudaEventDisableTiming);
    cudaEventCreateWithFlags(&evJoin, cudaEventDisableTiming);

    cudaEventRecord(evFork, 0);
    cudaStreamWaitEvent(s2, evFork, 0);

    // CSR build on s2
    k_init   <<<(NN + TB - 1) / TB, TB, 0, s2>>>();
    k_count  <<<(EE + TB - 1) / TB, TB, 0, s2>>>(ei);
    k_partial<<<NB, 256, 0, s2>>>();
    k_rowptr <<<NB, 256, 0, s2>>>();
    k_fill   <<<(EE + TB - 1) / TB, TB, 0, s2>>>(ei);
    cudaEventRecord(evJoin, s2);

    // GEMM1 on main stream, concurrent with CSR build
    k_gemm_h<false, false><<<gemm_grid, TB, GEMM_SMEM>>>(x, W1, h0);

    // join: aggregation needs CSR + GEMM1
    cudaStreamWaitEvent(0, evJoin, 0);

    k_agg<<<agg_grid, TB>>>(h0, b1, h1);
    // layer 2
    k_gemm_h<true, true><<<gemm_grid, TB, GEMM_SMEM>>>(h1, W2, h0);
    k_agg<<<agg_grid, TB>>>(h0, b2, h1);
    // layer 3 (agg fused with pool)
    k_gemm_h<true, true><<<gemm_grid, TB, GEMM_SMEM>>>(h1, W3, h0);
    k_agg_pool<<<agg_grid, TB>>>(h0, b3, batch);

    // head
    k_final<<<1, 128>>>(Wl, bl, out);

    cudaEventDestroy(evFork);
    cudaEventDestroy(evJoin);
    cudaStreamDestroy(s2);
}